// round 17
// baseline (speedup 1.0000x reference)
#include <cuda_runtime.h>
#include <cuda_fp16.h>
#include <cstdint>
#include <cstddef>

#define TT 2048
#define BB 16
#define DD 64
#define EE 512
#define NN (BB*TT)

#define LOG2E8 0.18033688011112042f   // 0.125 * log2(e)

// ---------------------------------------------------------------------------
// Global scratch  (all MMA operands are fp16 hi-only; softmax self-consistent)
// ---------------------------------------------------------------------------
__device__ uint16_t g_qh[(size_t)NN * DD];       // q hi  (fp16), row-major [N][64]
__device__ uint16_t g_qTh[(size_t)NN * DD];      // q^T hi, [b][64][2048]
__device__ uint16_t g_wt[(size_t)DD * EE];       // Wq^T fp16 [64 d][512 k]
__device__ float    g_part[(size_t)NN * 16];     // per-(row, j-tile) exp partial sums

typedef unsigned long long ull;

// ---------------------------------------------------------------------------
// helpers
// ---------------------------------------------------------------------------
__device__ __forceinline__ uint32_t smem_u32(const void* p) {
    uint32_t a;
    asm("{ .reg .u64 t; cvta.to.shared.u64 t, %1; cvt.u32.u64 %0, t; }" : "=r"(a) : "l"(p));
    return a;
}
#define SWZ(o) ((o) ^ (((o) >> 3) & 0x70))

#define LDSM4(r0,r1,r2,r3,a) \
    asm volatile("ldmatrix.sync.aligned.m8n8.x4.shared.b16 {%0,%1,%2,%3}, [%4];" \
        : "=r"(r0),"=r"(r1),"=r"(r2),"=r"(r3) : "r"(a))

__device__ __forceinline__ void mma_f16(float* d, const uint32_t* a,
                                        uint32_t b0, uint32_t b1) {
    asm volatile("mma.sync.aligned.m16n8k16.row.col.f32.f16.f16.f32 "
        "{%0,%1,%2,%3}, {%4,%5,%6,%7}, {%8,%9}, {%0,%1,%2,%3};"
        : "+f"(d[0]),"+f"(d[1]),"+f"(d[2]),"+f"(d[3])
        : "r"(a[0]),"r"(a[1]),"r"(a[2]),"r"(a[3]), "r"(b0),"r"(b1));
}

#define CPA16(dst, src) \
    asm volatile("cp.async.cg.shared.global [%0], [%1], 16;" :: "r"(dst), "l"(src) : "memory")
#define CP_COMMIT() asm volatile("cp.async.commit_group;" ::: "memory")
#define CP_WAIT1()  asm volatile("cp.async.wait_group 1;" ::: "memory")

// ---------------------------------------------------------------------------
// k0: one-time Wq [512][64] fp32 -> g_wt [64][512] fp16 (smem transpose)
// ---------------------------------------------------------------------------
__global__ __launch_bounds__(256) void k0_wcvt(const float* __restrict__ Wq)
{
    __shared__ float ws[64][68];
    const int tid = threadIdx.x;
    const int k0 = blockIdx.x * 64;
    #pragma unroll
    for (int it = 0; it < 4; it++) {
        int idx = it*256 + tid;
        int r = idx >> 4, c4 = idx & 15;
        float4 v = *(const float4*)(Wq + (size_t)(k0 + r)*DD + c4*4);
        ws[r][c4*4+0] = v.x; ws[r][c4*4+1] = v.y;
        ws[r][c4*4+2] = v.z; ws[r][c4*4+3] = v.w;
    }
    __syncthreads();
    #pragma unroll
    for (int it = 0; it < 2; it++) {
        int idx = it*256 + tid;
        int d = idx >> 3, kg = idx & 7;
        uint32_t h[8];
        #pragma unroll
        for (int j = 0; j < 8; j++)
            h[j] = (uint32_t)__half_as_ushort(__float2half_rn(ws[kg*8 + j][d]));
        uint4 o;
        o.x = h[0]|(h[1]<<16); o.y = h[2]|(h[3]<<16);
        o.z = h[4]|(h[5]<<16); o.w = h[6]|(h[7]<<16);
        *(uint4*)(g_wt + (size_t)d*EE + k0 + kg*8) = o;
    }
}

// ---------------------------------------------------------------------------
// K1: q = x @ Wq + bq via fp16 HMMA, x 2-split (hi+lo), W from g_wt (fp16).
// grid 256 (128 rows each), 256 threads (8 warps, m16 each).
// ---------------------------------------------------------------------------
#define K1_AH 0
#define K1_AL 16384
#define K1_BT 32768
#define K1_BS 40960
#define K1_SMEM 41216

__global__ __launch_bounds__(256) void k1_proj(
    const float* __restrict__ x, const float* __restrict__ bq)
{
    extern __shared__ char smc[];
    const uint32_t sb = smem_u32(smc);
    float* bs = (float*)(smc + K1_BS);
    const int tid = threadIdx.x, lane = tid & 31, w = tid >> 5;
    const int r0 = blockIdx.x * 128;
    const int b = r0 >> 11;
    const int t0l = r0 & (TT - 1);

    if (tid < 64) bs[tid] = bq[tid];

    const int arow = lane & 15;
    const int acol = (lane & 16) >> 1;
    const int brow = (lane & 7) | ((lane & 16) >> 1);
    const int bcol = lane & 8;

    float acc[8][4];
    #pragma unroll
    for (int t = 0; t < 8; t++)
        #pragma unroll
        for (int e = 0; e < 4; e++) acc[t][e] = 0.f;

    for (int kc = 0; kc < 8; kc++) {
        __syncthreads();
        #pragma unroll
        for (int it = 0; it < 4; it++) {
            int idx = it*256 + tid;
            int r = idx >> 3, kg = idx & 7;
            const float* xp = x + (size_t)(r0 + r)*EE + kc*64 + kg*8;
            float4 v0 = *(const float4*)(xp);
            float4 v1 = *(const float4*)(xp + 4);
            float vv[8] = {v0.x,v0.y,v0.z,v0.w,v1.x,v1.y,v1.z,v1.w};
            uint32_t h[8], l[8];
            #pragma unroll
            for (int q2 = 0; q2 < 8; q2++) {
                __half hh = __float2half_rn(vv[q2]);
                h[q2] = (uint32_t)__half_as_ushort(hh);
                l[q2] = (uint32_t)__half_as_ushort(__float2half_rn(vv[q2] - __half2float(hh)));
            }
            uint4 uh, ul;
            uh.x = h[0]|(h[1]<<16); uh.y = h[2]|(h[3]<<16);
            uh.z = h[4]|(h[5]<<16); uh.w = h[6]|(h[7]<<16);
            ul.x = l[0]|(l[1]<<16); ul.y = l[2]|(l[3]<<16);
            ul.z = l[4]|(l[5]<<16); ul.w = l[6]|(l[7]<<16);
            *(uint4*)(smc + K1_AH + SWZ(r*128 + kg*16)) = uh;
            *(uint4*)(smc + K1_AL + SWZ(r*128 + kg*16)) = ul;
        }
        #pragma unroll
        for (int it = 0; it < 2; it++) {
            int idx = it*256 + tid;
            int d = idx >> 3, kg = idx & 7;
            uint4 uh = *(const uint4*)(g_wt + (size_t)d*EE + kc*64 + kg*8);
            *(uint4*)(smc + K1_BT + SWZ(d*128 + kg*16)) = uh;
        }
        __syncthreads();
        #pragma unroll
        for (int ks = 0; ks < 4; ks++) {
            uint32_t ah[4], al[4], bbw[4][4];
            LDSM4(ah[0], ah[1], ah[2], ah[3],
                  sb + K1_AH + SWZ((w*16 + arow)*128 + (ks*16 + acol)*2));
            LDSM4(al[0], al[1], al[2], al[3],
                  sb + K1_AL + SWZ((w*16 + arow)*128 + (ks*16 + acol)*2));
            #pragma unroll
            for (int ng = 0; ng < 4; ng++)
                LDSM4(bbw[ng][0], bbw[ng][1], bbw[ng][2], bbw[ng][3],
                      sb + K1_BT + SWZ((ng*16 + brow)*128 + (ks*16 + bcol)*2));
            #pragma unroll
            for (int nt = 0; nt < 8; nt++)
                mma_f16(acc[nt], ah, bbw[nt>>1][(nt&1)*2], bbw[nt>>1][(nt&1)*2+1]);
            #pragma unroll
            for (int nt = 0; nt < 8; nt++)
                mma_f16(acc[nt], al, bbw[nt>>1][(nt&1)*2], bbw[nt>>1][(nt&1)*2+1]);
        }
    }
    __syncthreads();

    uint16_t* st = (uint16_t*)smc;   // [64 d][132 rows]
    const int g = lane >> 2;
    const int c2 = (lane & 3) * 2;
    #pragma unroll
    for (int nt = 0; nt < 8; nt++) {
        int col = nt*8 + c2;
        float b0 = bs[col], b1 = bs[col+1];
        uint32_t h00 = (uint32_t)__half_as_ushort(__float2half_rn(acc[nt][0] + b0));
        uint32_t h01 = (uint32_t)__half_as_ushort(__float2half_rn(acc[nt][1] + b1));
        uint32_t h10 = (uint32_t)__half_as_ushort(__float2half_rn(acc[nt][2] + b0));
        uint32_t h11 = (uint32_t)__half_as_ushort(__float2half_rn(acc[nt][3] + b1));
        int row = w*16 + g;
        *(uint32_t*)(g_qh + (size_t)(r0 + row)*DD + col)     = h00 | (h01 << 16);
        *(uint32_t*)(g_qh + (size_t)(r0 + row + 8)*DD + col) = h10 | (h11 << 16);
        st[col*132 + row]         = (uint16_t)h00;
        st[(col+1)*132 + row]     = (uint16_t)h01;
        st[col*132 + row + 8]     = (uint16_t)h10;
        st[(col+1)*132 + row + 8] = (uint16_t)h11;
    }
    __syncthreads();
    #pragma unroll
    for (int it = 0; it < 4; it++) {
        int idx = it*256 + tid;
        int d = idx >> 4, tg = idx & 15;
        uint32_t u[8];
        #pragma unroll
        for (int t2 = 0; t2 < 8; t2++) u[t2] = (uint32_t)st[d*132 + tg*8 + t2];
        uint4 o;
        o.x = u[0]|(u[1]<<16); o.y = u[2]|(u[3]<<16);
        o.z = u[4]|(u[5]<<16); o.w = u[6]|(u[7]<<16);
        *(uint4*)(g_qTh + ((size_t)b*DD + d)*TT + t0l + tg*8) = o;
    }
}

// ---------------------------------------------------------------------------
// KA: stats. S̃ = qh_i . qh_j^T (consistent with KB); exp2 partial sums.
// grid (136, 16), 256 threads.
// ---------------------------------------------------------------------------
#define KA_SMEM (32768 + 2048 + 1024)

__global__ __launch_bounds__(256) void ka_stats()
{
    extern __shared__ char smc[];
    float* rowpart = (float*)(smc + 32768);
    float* colpart = (float*)(smc + 32768 + 2048);
    const uint32_t sb = smem_u32(smc);
    const int tid = threadIdx.x, lane = tid & 31, w = tid >> 5;
    const int b = blockIdx.y;
    int jy = 0, rem = blockIdx.x;
    while (rem >= 16 - jy) { rem -= 16 - jy; jy++; }
    const int ix = jy + rem;
    const int i0 = ix * 128, j0 = jy * 128;

    #pragma unroll
    for (int it = 0; it < 8; it++) {
        int idx = it*256 + tid;
        int tile = idx >> 10;
        int r = (idx >> 3) & 127, ch = idx & 7;
        int grow = (tile == 0) ? (i0 + r) : (j0 + r);
        uint4 v = *(const uint4*)(g_qh + ((size_t)(b*TT + grow))*DD + ch*8);
        *(uint4*)(smc + tile*16384 + SWZ(r*128 + ch*16)) = v;
    }
    __syncthreads();

    const int wm = w >> 2, wn = w & 3;
    const int arow = lane & 15;
    const int acol = (lane & 16) >> 1;
    const int brow = (lane & 7) | ((lane & 16) >> 1);
    const int bcol = lane & 8;
    const int r_i = lane >> 2;
    const bool diag = (ix == jy);

    uint32_t bb[4][2][4];
    #pragma unroll
    for (int ks = 0; ks < 4; ks++)
        #pragma unroll
        for (int ng = 0; ng < 2; ng++)
            LDSM4(bb[ks][ng][0], bb[ks][ng][1], bb[ks][ng][2], bb[ks][ng][3],
                  sb + 16384 + SWZ((wn*32 + ng*16 + brow)*128 + (ks*16 + bcol)*2));

    float rp[4][2], cp[4][2];
    #pragma unroll
    for (int t = 0; t < 4; t++) { rp[t][0]=rp[t][1]=0.f; cp[t][0]=cp[t][1]=0.f; }

    #pragma unroll
    for (int mt = 0; mt < 4; mt++) {
        float d[4][4];
        #pragma unroll
        for (int t = 0; t < 4; t++)
            #pragma unroll
            for (int e = 0; e < 4; e++) d[t][e] = 0.f;
        #pragma unroll
        for (int ks = 0; ks < 4; ks++) {
            uint32_t a[4];
            LDSM4(a[0], a[1], a[2], a[3],
                  sb + SWZ((wm*64 + mt*16 + arow)*128 + (ks*16 + acol)*2));
            #pragma unroll
            for (int nt = 0; nt < 4; nt++)
                mma_f16(d[nt], a, bb[ks][nt>>1][(nt&1)*2], bb[ks][nt>>1][(nt&1)*2+1]);
        }
        #pragma unroll
        for (int nt = 0; nt < 4; nt++) {
            float e0 = exp2f(d[nt][0]*LOG2E8);
            float e1 = exp2f(d[nt][1]*LOG2E8);
            float e2 = exp2f(d[nt][2]*LOG2E8);
            float e3 = exp2f(d[nt][3]*LOG2E8);
            rp[mt][0] += e0 + e1;  rp[mt][1] += e2 + e3;
            cp[nt][0] += e0 + e2;  cp[nt][1] += e1 + e3;
        }
    }

    #pragma unroll
    for (int mt = 0; mt < 4; mt++) {
        float r0 = rp[mt][0], r1 = rp[mt][1];
        r0 += __shfl_xor_sync(0xffffffffu, r0, 1); r0 += __shfl_xor_sync(0xffffffffu, r0, 2);
        r1 += __shfl_xor_sync(0xffffffffu, r1, 1); r1 += __shfl_xor_sync(0xffffffffu, r1, 2);
        if ((lane & 3) == 0) {
            int rl = wm*64 + mt*16 + r_i;
            rowpart[wn*128 + rl]     = r0;
            rowpart[wn*128 + rl + 8] = r1;
        }
    }
    #pragma unroll
    for (int nt = 0; nt < 4; nt++) {
        float c0 = cp[nt][0], c1 = cp[nt][1];
        c0 += __shfl_xor_sync(0xffffffffu, c0, 4); c0 += __shfl_xor_sync(0xffffffffu, c0, 8);
        c0 += __shfl_xor_sync(0xffffffffu, c0, 16);
        c1 += __shfl_xor_sync(0xffffffffu, c1, 4); c1 += __shfl_xor_sync(0xffffffffu, c1, 8);
        c1 += __shfl_xor_sync(0xffffffffu, c1, 16);
        if (lane < 4) {
            int cl = wn*32 + nt*8 + lane*2;
            colpart[wm*128 + cl]     = c0;
            colpart[wm*128 + cl + 1] = c1;
        }
    }
    __syncthreads();

    if (tid < 128) {
        float rs = rowpart[tid] + rowpart[128+tid] + rowpart[256+tid] + rowpart[384+tid];
        g_part[((size_t)(b*TT + i0 + tid))*16 + jy] = rs;
        if (!diag) {
            float cs = colpart[tid] + colpart[128+tid];
            g_part[((size_t)(b*TT + j0 + tid))*16 + ix] = cs;
        }
    }
}

// ---------------------------------------------------------------------------
// KB: fused out = P.q; S̃ recomputed (consistent with KA), P fp16 via exp2;
// c2 = log2(sum g_part) computed INLINE per chunk (k3 kernel eliminated).
// i-tile 256, 8 warps x m32, q_i A-fragments cached in registers.
// grid (8 i-tiles, 16 b) = 128 CTAs, 256 threads, 1 CTA/SM.
// ---------------------------------------------------------------------------
#define KB_STRIDE 20736
#define QJH(buf)  ((buf)*KB_STRIDE)
#define QTH(buf)  ((buf)*KB_STRIDE + 8192)
#define PBUF(buf) ((buf)*KB_STRIDE + 16384)   // 4 KB: g_part rows for this chunk
#define CB2(buf)  ((buf)*KB_STRIDE + 20480)   // 256 B: c2[j] for this chunk
#define QI_H (2*KB_STRIDE)
#define KB_SMEM (2*KB_STRIDE + 32768)

__global__ __launch_bounds__(256, 1) void kb_fused(float* __restrict__ out)
{
    extern __shared__ char smc[];
    const uint32_t sb = smem_u32(smc);
    const int tid = threadIdx.x, lane = tid & 31, w = tid >> 5;
    const int i0 = blockIdx.x * 256, b = blockIdx.y;

    const uint16_t* qh  = g_qh  + (size_t)b * TT * DD;
    const uint16_t* qTh = g_qTh + (size_t)b * DD * TT;
    const float*    pb  = g_part + (size_t)b * TT * 16;

    #pragma unroll
    for (int it = 0; it < 8; it++) {
        int idx = it*256 + tid;
        int r = idx >> 3, seg = idx & 7;
        *(uint4*)(smc + QI_H + SWZ(r*128 + seg*16)) =
            *(const uint4*)(qh + (size_t)(i0 + r)*DD + seg*8);
    }

    auto prefetch = [&](int c, int buf) {
        const int j0c = c * 64;
        #pragma unroll
        for (int k2 = 0; k2 < 2; k2++) {
            int idx = k2*256 + tid;
            int r = idx >> 3, seg = idx & 7;
            CPA16(sb + QJH(buf) + SWZ(r*128 + seg*16),
                  (const void*)(qh + (size_t)(j0c + r)*DD + seg*8));
            CPA16(sb + QTH(buf) + SWZ(r*128 + seg*16),
                  (const void*)(qTh + (size_t)r*TT + j0c + seg*8));
        }
        CPA16(sb + PBUF(buf) + tid*16, (const void*)(pb + (size_t)j0c*16 + tid*4));
    };

    prefetch(0, 0); CP_COMMIT();
    prefetch(1, 1); CP_COMMIT();
    __syncthreads();

    const int arow = lane & 15;
    const int acol = (lane & 16) >> 1;
    const int brow = (lane & 7) | ((lane & 16) >> 1);
    const int bcol = lane & 8;

    uint32_t aq[2][4][4];
    #pragma unroll
    for (int mt = 0; mt < 2; mt++)
        #pragma unroll
        for (int ks = 0; ks < 4; ks++)
            LDSM4(aq[mt][ks][0], aq[mt][ks][1], aq[mt][ks][2], aq[mt][ks][3],
                  sb + QI_H + SWZ((w*32 + mt*16 + arow)*128 + (ks*16 + acol)*2));

    float o[2][8][4];
    #pragma unroll
    for (int mt = 0; mt < 2; mt++)
        #pragma unroll
        for (int t = 0; t < 8; t++)
            #pragma unroll
            for (int e = 0; e < 4; e++) o[mt][t][e] = 0.f;

    for (int c = 0; c < 32; c++) {
        const int buf = c & 1;
        CP_WAIT1();
        __syncthreads();

        // inline c2 = log2(sum of 16 partials) for the 64 j's of this chunk
        if (tid < 64) {
            const float4* pp = (const float4*)(smc + PBUF(buf) + tid*64);
            float4 a4 = pp[0], b4 = pp[1], c4 = pp[2], e4 = pp[3];
            float s = a4.x + a4.y + a4.z + a4.w;
            s += b4.x + b4.y + b4.z + b4.w;
            s += c4.x + c4.y + c4.z + c4.w;
            s += e4.x + e4.y + e4.z + e4.w;
            *(float*)(smc + CB2(buf) + tid*4) = log2f(s);
        }
        __syncthreads();

        #pragma unroll
        for (int half = 0; half < 2; half++) {
            float s[2][4][4];
            #pragma unroll
            for (int mt = 0; mt < 2; mt++)
                #pragma unroll
                for (int t = 0; t < 4; t++)
                    #pragma unroll
                    for (int e = 0; e < 4; e++) s[mt][t][e] = 0.f;

            #pragma unroll
            for (int ks = 0; ks < 4; ks++) {
                uint32_t bb[2][4];
                #pragma unroll
                for (int ng = 0; ng < 2; ng++)
                    LDSM4(bb[ng][0], bb[ng][1], bb[ng][2], bb[ng][3],
                          sb + QJH(buf) + SWZ((half*32 + ng*16 + brow)*128 + (ks*16 + bcol)*2));
                #pragma unroll
                for (int mt = 0; mt < 2; mt++)
                    #pragma unroll
                    for (int nt = 0; nt < 4; nt++)
                        mma_f16(s[mt][nt], aq[mt][ks],
                                bb[nt>>1][(nt&1)*2], bb[nt>>1][(nt&1)*2+1]);
            }

            uint32_t ph01[2][4], ph23[2][4];
            #pragma unroll
            for (int mt = 0; mt < 2; mt++) {
                #pragma unroll
                for (int nt = 0; nt < 4; nt++) {
                    float2 cv = *(const float2*)(smc + CB2(buf) + (half*32 + nt*8 + (lane&3)*2)*4);
                    float p0 = exp2f(fmaf(s[mt][nt][0], LOG2E8, -cv.x));
                    float p1 = exp2f(fmaf(s[mt][nt][1], LOG2E8, -cv.y));
                    float p2 = exp2f(fmaf(s[mt][nt][2], LOG2E8, -cv.x));
                    float p3 = exp2f(fmaf(s[mt][nt][3], LOG2E8, -cv.y));
                    uint16_t h0 = __half_as_ushort(__float2half_rn(p0));
                    uint16_t h1 = __half_as_ushort(__float2half_rn(p1));
                    uint16_t h2 = __half_as_ushort(__float2half_rn(p2));
                    uint16_t h3 = __half_as_ushort(__float2half_rn(p3));
                    ph01[mt][nt] = (uint32_t)h0 | ((uint32_t)h1 << 16);
                    ph23[mt][nt] = (uint32_t)h2 | ((uint32_t)h3 << 16);
                }
            }

            #pragma unroll
            for (int ks2 = 0; ks2 < 2; ks2++) {
                uint32_t bb[4][4];
                #pragma unroll
                for (int ng = 0; ng < 4; ng++)
                    LDSM4(bb[ng][0], bb[ng][1], bb[ng][2], bb[ng][3],
                          sb + QTH(buf) + SWZ((ng*16 + brow)*128 + (half*32 + ks2*16 + bcol)*2));
                #pragma unroll
                for (int mt = 0; mt < 2; mt++) {
                    uint32_t a2[4] = { ph01[mt][2*ks2], ph23[mt][2*ks2],
                                       ph01[mt][2*ks2+1], ph23[mt][2*ks2+1] };
                    #pragma unroll
                    for (int nt2 = 0; nt2 < 8; nt2++)
                        mma_f16(o[mt][nt2], a2,
                                bb[nt2>>1][(nt2&1)*2], bb[nt2>>1][(nt2&1)*2+1]);
                }
            }
        }

        __syncthreads();
        if (c + 2 < 32) prefetch(c + 2, buf);
        CP_COMMIT();
    }

    const int g = lane >> 2;
    const int t2 = (lane & 3) * 2;
    #pragma unroll
    for (int mt = 0; mt < 2; mt++) {
        #pragma unroll
        for (int nt2 = 0; nt2 < 8; nt2++) {
            int row = i0 + w*32 + mt*16 + g;
            int col = nt2*8 + t2;
            *(float2*)(out + ((size_t)b*TT + row)*DD + col) =
                make_float2(o[mt][nt2][0], o[mt][nt2][1]);
            *(float2*)(out + ((size_t)b*TT + row + 8)*DD + col) =
                make_float2(o[mt][nt2][2], o[mt][nt2][3]);
        }
    }
}

// ---------------------------------------------------------------------------
extern "C" void kernel_launch(void* const* d_in, const int* in_sizes, int n_in,
                              void* d_out, int out_size)
{
    const float* x  = (const float*)d_in[0];
    const float* Wq = (const float*)d_in[1];
    const float* bq = (const float*)d_in[2];
    float* out = (float*)d_out;

    cudaFuncSetAttribute(k1_proj,  cudaFuncAttributeMaxDynamicSharedMemorySize, K1_SMEM);
    cudaFuncSetAttribute(ka_stats, cudaFuncAttributeMaxDynamicSharedMemorySize, KA_SMEM);
    cudaFuncSetAttribute(kb_fused, cudaFuncAttributeMaxDynamicSharedMemorySize, KB_SMEM);

    k0_wcvt<<<EE/64, 256>>>(Wq);
    k1_proj<<<NN/128, 256, K1_SMEM>>>(x, bq);
    ka_stats<<<dim3(136, BB), 256, KA_SMEM>>>();
    kb_fused<<<dim3(TT/256, BB), 256, KB_SMEM>>>(out);
}